// round 17
// baseline (speedup 1.0000x reference)
#include <cuda_runtime.h>
#include <cstdint>

// MobiusFlow4ND — 4 pairs per warp (8 lanes per pair), 21 warps per block.
// Block = 84 pairs = 4 batch rows; grid = B/4 = 1024.
//
// R16 = R13 (best, 26.85us: prefetch-pipelined k-loop, single-phase cp.async
// staging, 2 blocks/SM) with the k-loop SCALARIZED via hoisted frame dots:
//   x.r = -|x|, x.v = 0, h = f*x - sc(1+f)*wp  =>
//   hv = -sc(1+f)(wp.v), hr = -f|x| - sc(1+f)(wp.r)
//   wp.v = w.v - d(y.v), wp.r = w.r - d(y.r), x.wp = -|x|(w.r) - d(x.y)
//   |wp|^2 = w.w + (|y|^2-2)d^2, |zw|^2 = |x|^2 - 2sc(x.wp) + sc^2|wp|^2
// Per-k vector work = 4 independent depth-3 dot products; the rest is a thin
// scalar chain (R15 showed the chain can't be widened at this reg budget, so
// shorten/thin it instead).

#define NPER 21
#define PAIRS_PER_BLOCK 84      // 21 warps * 4 groups
#define ROWS_PER_BLOCK 4
#define ROW_F 264               // padded row stride in floats (1056 B; mod 32 = 8)
#define SMEM_FLOATS (PAIRS_PER_BLOCK * ROW_F)
#define SMEM_BYTES  (SMEM_FLOATS * 4 + PAIRS_PER_BLOCK * 4)
#define TWO_PI 6.28318530717958647692f
#define PI_F   3.14159265358979323846f
#define HALF_PI 1.57079632679489661923f

__device__ __forceinline__ void cp16(uint32_t dst, const char* src) {
    asm volatile("cp.async.cg.shared.global [%0], [%1], 16;" :: "r"(dst), "l"(src));
}

// atan2(y,x) mapped to [0, 2pi): q = |atan2| in [0,pi]; result = y>=0 ? q : 2pi-q.
__device__ __forceinline__ float ang02pi(float y, float x) {
    float ax = fabsf(x), ay = fabsf(y);
    float hi = fmaxf(ax, ay);
    float lo = fminf(ax, ay);
    float a  = (hi > 0.0f) ? __fdividef(lo, hi) : 0.0f;
    float s  = a * a;
    // minimax atan on [0,1], max err ~1e-5 rad
    float p = 0.0208351f;
    p = fmaf(p, s, -0.0851330f);
    p = fmaf(p, s,  0.1801410f);
    p = fmaf(p, s, -0.3302995f);
    p = fmaf(p, s,  0.9998660f);
    p = p * a;
    if (ay > ax)  p = HALF_PI - p;
    if (x < 0.0f) p = PI_F - p;          // now p = q in [0, pi]
    return (y >= 0.0f) ? p : TWO_PI - p;
}

__device__ __forceinline__ float softplus_f(float t) {
    return (t > 15.0f) ? t : __logf(1.0f + __expf(t));
}

// permute arrives either as 3 x int32 or 3 x int64 (little-endian words).
__device__ __forceinline__ void decode_perm(const int* pi, int& p0, int& p1, int& p2) {
    int a = pi[0], b = pi[1], c = pi[2];
    bool is32 = (a >= 0 && a < 3) && (b >= 0 && b < 3) && (c >= 0 && c < 3) &&
                (a != b) && (b != c) && (a != c);
    if (is32) { p0 = a; p1 = b; p2 = c; }
    else      { p0 = pi[0]; p1 = pi[2]; p2 = pi[4]; }
}

__global__ __launch_bounds__(672, 2)
void mobius_kernel(const float* __restrict__ rot,
                   const float* __restrict__ cond,
                   const int* __restrict__ perm,
                   float* __restrict__ out,
                   long long ldj_off,
                   long long npairs,
                   int B)
{
    extern __shared__ float smem[];
    float* sldj = smem + SMEM_FLOATS;

    const int tid  = threadIdx.x;
    const int lane = tid & 31;
    const int wid  = tid >> 5;           // warp 0..20
    const int g    = lane >> 3;          // group within warp: 0..3
    const int gl   = lane & 7;           // lane within group: 0..7
    const int bp   = wid * 4 + g;        // pair index within block: 0..83

    long long pair = (long long)blockIdx.x * PAIRS_PER_BLOCK + bp;
    const bool active = pair < npairs;
    if (!active) pair = 0;               // clamp; stores guarded

    long long warpPair0 = (long long)blockIdx.x * PAIRS_PER_BLOCK + wid * 4;
    if (warpPair0 > npairs - 4) warpPair0 = npairs - 4;
    const char* warpSrc = (const char*)(cond + warpPair0 * 256);

    // ---- Hoisted single-phase staging: this warp's 4 contiguous rows (4KB).
    uint32_t sbase = (uint32_t)__cvta_generic_to_shared(smem);
    const uint32_t dstB = sbase + (uint32_t)(wid * 4) * 1056u + (uint32_t)lane * 16u;
    const char*    srcB = warpSrc + lane * 16;
    cp16(dstB + 0,    srcB + 0);
    cp16(dstB + 512,  srcB + 512);
    cp16(dstB + 1056, srcB + 1024);
    cp16(dstB + 1568, srcB + 1536);
    cp16(dstB + 2112, srcB + 2048);
    cp16(dstB + 2624, srcB + 2560);
    cp16(dstB + 3168, srcB + 3072);
    cp16(dstB + 3680, srcB + 3584);
    asm volatile("cp.async.commit_group;");

    int p0, p1, p2;
    decode_perm(perm, p0, p1, p2);

    // ---- Frame computation overlaps the cp.async flight ----
    const float* rp = rot + pair * 9;
    float x0 = __ldg(rp + 0 * 3 + p0), x1 = __ldg(rp + 1 * 3 + p0), x2 = __ldg(rp + 2 * 3 + p0);
    float y0 = __ldg(rp + 0 * 3 + p1), y1 = __ldg(rp + 1 * 3 + p1), y2 = __ldg(rp + 2 * 3 + p1);

    float xx  = fmaf(x0, x0, fmaf(x1, x1, x2 * x2));
    float inx = rsqrtf(xx);
    float xnorm = xx * inx;              // |x|
    float r0 = -x0 * inx, r1 = -x1 * inx, r2 = -x2 * inx;
    float v0 = fmaf(y1, r2, -y2 * r1);
    float v1 = fmaf(y2, r0, -y0 * r2);
    float v2 = fmaf(y0, r1, -y1 * r0);
    float inv = rsqrtf(fmaf(v0, v0, fmaf(v1, v1, v2 * v2)));
    v0 *= inv; v1 *= inv; v2 *= inv;

    // Hoisted frame scalars for the scalarized loop
    float xy   = fmaf(x0, y0, fmaf(x1, y1, x2 * y2));     // x.y
    float yy   = fmaf(y0, y0, fmaf(y1, y1, y2 * y2));     // |y|^2
    float c2ym = yy - 2.0f;                                // (|y|^2 - 2)
    float yr   = fmaf(y0, r0, fmaf(y1, r1, y2 * r2));     // y.r
    float yv   = fmaf(y0, v0, fmaf(y1, v1, y2 * v2));     // y.v (~0)

    asm volatile("cp.async.wait_group 0;");
    __syncwarp();

    const float* myrow = smem + bp * ROW_F;

    float S = 0.0f, A = 0.0f, G = 0.0f;

    // ---- Software-pipelined scalarized k-loop ----
    float spRaw = myrow[gl];
    float nw0 = myrow[64 + 3 * gl + 0];
    float nw1 = myrow[64 + 3 * gl + 1];
    float nw2 = myrow[64 + 3 * gl + 2];

    #pragma unroll
    for (int it = 0; it < 8; ++it) {
        float spc = spRaw;
        float w0 = nw0, w1 = nw1, w2 = nw2;

        float sp = softplus_f(spc);      // independent MUFU chain

        // four parallel depth-3 dot products on raw w
        float d  = fmaf(y0, w0, fmaf(y1, w1, y2 * w2));
        float cv = fmaf(v0, w0, fmaf(v1, w1, v2 * w2));
        float cr = fmaf(r0, w0, fmaf(r1, w1, r2 * w2));
        float ww = fmaf(w0, w0, fmaf(w1, w1, w2 * w2));

        // ---- prefetch next iteration's operands (w regs dead from here) ----
        if (it < 7) {
            const int kn = gl + (it + 1) * 8;
            spRaw = myrow[kn];
            nw0 = myrow[64 + 3 * kn + 0];
            nw1 = myrow[64 + 3 * kn + 1];
            nw2 = myrow[64 + 3 * kn + 2];
        }

        // |wp|^2 = ww + (yy-2) d^2
        float dd   = d * d;
        float wn2r = fmaf(c2ym, dd, ww);
        float wn   = (wn2r > 0.0f) ? wn2r * rsqrtf(wn2r) : 0.0f;
        float sc   = __fdividef(0.7f, 1.0f + wn);

        float scc = sc * sc;
        float wn2 = scc * wn2r;                       // |w|^2 after scaling

        // x.wp = -|x|*cr - d*xy ; |zw|^2 = xx - 2 sc (x.wp) + sc^2 |wp|^2
        float xwp = fmaf(-xy, d, -xnorm * cr);
        float zn2 = fmaf(-2.0f * sc, xwp, xx) + wn2;
        float f   = __fdividef(1.0f - wn2, zn2);

        // h.v / h.r via scalars: u = sc(1+f)
        float u   = fmaf(sc, f, sc);
        float wpv = fmaf(-yv, d, cv);
        float wpr = fmaf(-yr, d, cr);
        float hv  = -u * wpv;
        float hr  = fmaf(-u, wpr, -f * xnorm);

        float ang = ang02pi(hv, hr);

        S += sp;
        A = fmaf(sp, ang, A);
        G = fmaf(sp, f, G);   // |dh_dtheta| == f (Householder preserves unit norm)
    }

    // reduce S, A, G over the 8-lane group
    #pragma unroll
    for (int off = 4; off; off >>= 1) {
        S += __shfl_xor_sync(0xFFFFFFFFu, S, off);
        A += __shfl_xor_sync(0xFFFFFFFFu, A, off);
        G += __shfl_xor_sync(0xFFFFFFFFu, G, off);
    }

    float invS = __fdividef(1.0f, S);
    float ang  = A * invS;
    float sA, cA;
    __sincosf(ang, &sA, &cA);

    float tx0 = fmaf(r0, cA, v0 * sA);
    float tx1 = fmaf(r1, cA, v1 * sA);
    float tx2 = fmaf(r2, cA, v2 * sA);

    float ldj = __logf(G * invS);

    // tz = cross(tx, y) if (p1-p0==1 || p1-p0==-2) else cross(y, tx); normalized
    int dp = p1 - p0;
    bool fwd = (dp == 1) || (dp == -2);
    float a0, a1, a2, b0, b1, b2;
    if (fwd) { a0 = tx0; a1 = tx1; a2 = tx2; b0 = y0;  b1 = y1;  b2 = y2;  }
    else     { a0 = y0;  a1 = y1;  a2 = y2;  b0 = tx0; b1 = tx1; b2 = tx2; }
    float tz0 = fmaf(a1, b2, -a2 * b1);
    float tz1 = fmaf(a2, b0, -a0 * b2);
    float tz2 = fmaf(a0, b1, -a1 * b0);
    float itz = rsqrtf(fmaf(tz0, tz0, fmaf(tz1, tz1, tz2 * tz2)));
    tz0 *= itz; tz1 *= itz; tz2 *= itz;

    // Group leader stores the 3x3 (9 STG issues serve 4 pairs each).
    if (gl == 0 && active) {
        float* op = out + pair * 9;
        op[0 * 3 + p0] = tx0; op[1 * 3 + p0] = tx1; op[2 * 3 + p0] = tx2;
        op[0 * 3 + p1] = y0;  op[1 * 3 + p1] = y1;  op[2 * 3 + p1] = y2;
        op[0 * 3 + p2] = tz0; op[1 * 3 + p2] = tz1; op[2 * 3 + p2] = tz2;
    }

    // Deterministic ldj row-sums: 84 pairs = 4 rows per block.
    if (gl == 0) sldj[bp] = active ? ldj : 0.0f;
    __syncthreads();
    if (tid < ROWS_PER_BLOCK) {
        long long row = (long long)blockIdx.x * ROWS_PER_BLOCK + tid;
        if (row < B) {
            float s = 0.0f;
            #pragma unroll
            for (int i = 0; i < NPER; ++i) s += sldj[tid * NPER + i];
            out[ldj_off + row] = s;
        }
    }
}

extern "C" void kernel_launch(void* const* d_in, const int* in_sizes, int n_in,
                              void* d_out, int out_size) {
    const float* rot  = (const float*)d_in[0];
    const float* cond = (const float*)d_in[1];
    const int*   perm = (const int*)d_in[2];
    float* out = (float*)d_out;

    const long long rot_elems = in_sizes[0];          // B*N*9
    const long long npairs    = rot_elems / 9;        // B*N
    const int B = (int)(npairs / NPER);               // 4096
    const long long ldj_off = rot_elems;              // trotation first, then ldj[B]

    // One-time, pre-capture (first call is the harness's correctness run).
    static bool attr_set = false;
    if (!attr_set) {
        cudaFuncSetAttribute(mobius_kernel,
                             cudaFuncAttributeMaxDynamicSharedMemorySize,
                             SMEM_BYTES);
        attr_set = true;
    }

    const int grid = (int)((npairs + PAIRS_PER_BLOCK - 1) / PAIRS_PER_BLOCK);
    mobius_kernel<<<grid, 672, SMEM_BYTES>>>(rot, cond, perm, out, ldj_off, npairs, B);
}